// round 1
// baseline (speedup 1.0000x reference)
#include <cuda_runtime.h>
#include <math.h>

// Problem dims (fixed)
#define BB 2
#define TT 2048
#define CC 1024
#define NHH 16
#define HDD 64
#define MTOK 4096          // B*T
#define C3 3072
#define C4 4096

// ---------------- scratch (no allocation allowed) ----------------
__device__ float g_qkv[(size_t)MTOK * C3];
__device__ float g_att[(size_t)MTOK * CC];
__device__ float g_h  [(size_t)MTOK * C4];
__device__ float g_x1 [(size_t)MTOK * CC];
__device__ float g_y  [(size_t)MTOK * CC];

__device__ __forceinline__ float gelu_f(float v) {
    return 0.5f * v * (1.0f + erff(v * 0.7071067811865475f));
}

// ---------------- GEMM: C = A(MxK) @ B(KxN) + bias, optional exact GELU ----
// BM=BN=128, BK=8, 256 threads, 8x8 per-thread tile, double-buffered smem.
template<bool GELU_EP>
__global__ void __launch_bounds__(256)
gemm_bias_kernel(const float* __restrict__ A, const float* __restrict__ B,
                 const float* __restrict__ bias, float* __restrict__ C,
                 int N, int K)
{
    __shared__ float As[2][8][128];
    __shared__ float Bs[2][8][128];

    const int t  = threadIdx.x;
    const int bm = blockIdx.y * 128;
    const int bn = blockIdx.x * 128;

    const int ar = t >> 1;            // 0..127
    const int ak = (t & 1) * 4;       // 0 or 4
    const int br = t >> 5;            // 0..7
    const int bc = (t & 31) * 4;      // 0..124
    const int tr = (t >> 4) * 8;      // row base of 8x8 tile
    const int tc = (t & 15) * 8;      // col base of 8x8 tile

    const float* Aptr = A + (size_t)(bm + ar) * K + ak;
    const float* Bptr = B + (size_t)br * N + bn + bc;

    float acc[8][8];
#pragma unroll
    for (int i = 0; i < 8; ++i)
#pragma unroll
        for (int j = 0; j < 8; ++j) acc[i][j] = 0.0f;

    const int nk = K >> 3;
    float4 a4 = *(const float4*)Aptr;
    float4 b4 = *(const float4*)Bptr;

    for (int kt = 0; kt < nk; ++kt) {
        const int buf = kt & 1;
        As[buf][ak + 0][ar] = a4.x;
        As[buf][ak + 1][ar] = a4.y;
        As[buf][ak + 2][ar] = a4.z;
        As[buf][ak + 3][ar] = a4.w;
        *(float4*)&Bs[buf][br][bc] = b4;
        __syncthreads();

        if (kt + 1 < nk) {
            a4 = *(const float4*)(Aptr + (size_t)(kt + 1) * 8);
            b4 = *(const float4*)(Bptr + (size_t)(kt + 1) * 8 * N);
        }

#pragma unroll
        for (int k = 0; k < 8; ++k) {
            float av[8], bv[8];
            *(float4*)&av[0] = *(const float4*)&As[buf][k][tr];
            *(float4*)&av[4] = *(const float4*)&As[buf][k][tr + 4];
            *(float4*)&bv[0] = *(const float4*)&Bs[buf][k][tc];
            *(float4*)&bv[4] = *(const float4*)&Bs[buf][k][tc + 4];
#pragma unroll
            for (int i = 0; i < 8; ++i)
#pragma unroll
                for (int j = 0; j < 8; ++j)
                    acc[i][j] += av[i] * bv[j];
        }
    }

#pragma unroll
    for (int i = 0; i < 8; ++i) {
        float* cp = C + (size_t)(bm + tr + i) * N + bn + tc;
        float o[8];
#pragma unroll
        for (int j = 0; j < 8; ++j) {
            float v = acc[i][j] + bias[bn + tc + j];
            if (GELU_EP) v = gelu_f(v);
            o[j] = v;
        }
        *(float4*)&cp[0] = *(float4*)&o[0];
        *(float4*)&cp[4] = *(float4*)&o[4];
    }
}

// ---------------- causal attention, fp32, flash-style ----------------
// grid: (T/64, NH, B), 256 threads. 64-query x 64-key tiles, online softmax.
// qkv layout: [b*T + t][3C], split order K|Q|V, head h at col h*64.
#define ATT_SMEM_FLOATS (4160 + 4160 + 4096 + 192)
__global__ void __launch_bounds__(256)
attn_kernel(const float* __restrict__ qkv, float* __restrict__ out)
{
    extern __shared__ float sm[];
    float* Qs  = sm;            // [d*65 + r]  (64x64, pad 65)
    float* Ks  = sm + 4160;     // [d*65 + c], reused as P[r*65 + c]
    float* Vs  = sm + 8320;     // [k*64 + d]
    float* m_s = sm + 12416;    // 64
    float* l_s = m_s + 64;      // 64
    float* al_s = l_s + 64;     // 64

    const int t  = threadIdx.x;
    const int qb = blockIdx.x * 64;
    const int h  = blockIdx.y;
    const int b  = blockIdx.z;

    const float* base = qkv + (size_t)b * TT * C3 + h * HDD;
    const float* Kg = base;
    const float* Qg = base + CC;
    const float* Vg = base + 2 * CC;

    // load Q tile (transposed: d-major)
    for (int i = t; i < 1024; i += 256) {
        int r = i >> 4, d = (i & 15) * 4;
        float4 q = *(const float4*)&Qg[(size_t)(qb + r) * C3 + d];
        Qs[(d + 0) * 65 + r] = q.x;
        Qs[(d + 1) * 65 + r] = q.y;
        Qs[(d + 2) * 65 + r] = q.z;
        Qs[(d + 3) * 65 + r] = q.w;
    }
    if (t < 64) { m_s[t] = -1e30f; l_s[t] = 0.0f; }

    const int tr = t >> 4, tc = t & 15;
    const int r0 = tr * 4, c0 = tc * 4;

    float O[4][4];
#pragma unroll
    for (int i = 0; i < 4; ++i)
#pragma unroll
        for (int j = 0; j < 4; ++j) O[i][j] = 0.0f;

    const int ntiles = blockIdx.x + 1;
    for (int kt = 0; kt < ntiles; ++kt) {
        const int kb = kt * 64;
        __syncthreads();   // prior PV reads done before overwriting Ks/Vs
        for (int i = t; i < 1024; i += 256) {
            int c = i >> 4, d = (i & 15) * 4;
            float4 kv = *(const float4*)&Kg[(size_t)(kb + c) * C3 + d];
            Ks[(d + 0) * 65 + c] = kv.x;
            Ks[(d + 1) * 65 + c] = kv.y;
            Ks[(d + 2) * 65 + c] = kv.z;
            Ks[(d + 3) * 65 + c] = kv.w;
            *(float4*)&Vs[c * 64 + d] = *(const float4*)&Vg[(size_t)(kb + c) * C3 + d];
        }
        __syncthreads();

        // S = Q @ K^T (4x4 per thread)
        float S[4][4];
#pragma unroll
        for (int i = 0; i < 4; ++i)
#pragma unroll
            for (int j = 0; j < 4; ++j) S[i][j] = 0.0f;
#pragma unroll 4
        for (int d = 0; d < 64; ++d) {
            float qv[4], kv[4];
#pragma unroll
            for (int i = 0; i < 4; ++i) qv[i] = Qs[d * 65 + r0 + i];
#pragma unroll
            for (int j = 0; j < 4; ++j) kv[j] = Ks[d * 65 + c0 + j];
#pragma unroll
            for (int i = 0; i < 4; ++i)
#pragma unroll
                for (int j = 0; j < 4; ++j) S[i][j] += qv[i] * kv[j];
        }
        __syncthreads();  // everyone done reading Ks

        // scaled + masked -> P buffer (reuse Ks), layout [r][c]
#pragma unroll
        for (int i = 0; i < 4; ++i) {
            int q = qb + r0 + i;
#pragma unroll
            for (int j = 0; j < 4; ++j) {
                int k = kb + c0 + j;
                Ks[(r0 + i) * 65 + c0 + j] = (k <= q) ? S[i][j] * 0.125f : -1e30f;
            }
        }
        __syncthreads();

        // per-row online softmax (64 rows by threads 0..63)
        if (t < 64) {
            const int r = t;
            float mo = m_s[r];
            float rowmax = -1e30f;
            for (int c = 0; c < 64; ++c) rowmax = fmaxf(rowmax, Ks[r * 65 + c]);
            float mn = fmaxf(mo, rowmax);
            float a  = __expf(mo - mn);
            float s  = 0.0f;
            for (int c = 0; c < 64; ++c) {
                float p = __expf(Ks[r * 65 + c] - mn);
                Ks[r * 65 + c] = p;
                s += p;
            }
            l_s[r]  = l_s[r] * a + s;
            m_s[r]  = mn;
            al_s[r] = a;
        }
        __syncthreads();

        // O = O*alpha + P @ V
        float al[4];
#pragma unroll
        for (int i = 0; i < 4; ++i) al[i] = al_s[r0 + i];
#pragma unroll
        for (int i = 0; i < 4; ++i)
#pragma unroll
            for (int j = 0; j < 4; ++j) O[i][j] *= al[i];
#pragma unroll 4
        for (int k = 0; k < 64; ++k) {
            float pv[4];
#pragma unroll
            for (int i = 0; i < 4; ++i) pv[i] = Ks[(r0 + i) * 65 + k];
            float4 vv = *(const float4*)&Vs[k * 64 + c0];
#pragma unroll
            for (int i = 0; i < 4; ++i) {
                O[i][0] += pv[i] * vv.x;
                O[i][1] += pv[i] * vv.y;
                O[i][2] += pv[i] * vv.z;
                O[i][3] += pv[i] * vv.w;
            }
        }
    }

    // write: out[b, qb+r, h*64 + c]
#pragma unroll
    for (int i = 0; i < 4; ++i) {
        int r = r0 + i;
        float inv = 1.0f / l_s[r];
        float o[4];
#pragma unroll
        for (int j = 0; j < 4; ++j) o[j] = O[i][j] * inv;
        *(float4*)&out[((size_t)b * TT + qb + r) * CC + h * HDD + c0] = *(float4*)&o[0];
    }
}

// ---------------- LayerNorm + residual: out = res + ln(y)*g + be ----------
__device__ __forceinline__ float block_sum(float v, float* red) {
    const int lane = threadIdx.x & 31, w = threadIdx.x >> 5;
#pragma unroll
    for (int o = 16; o; o >>= 1) v += __shfl_xor_sync(0xffffffffu, v, o);
    if (lane == 0) red[w] = v;
    __syncthreads();
    if (w == 0) {
        float s = (lane < 8) ? red[lane] : 0.0f;
#pragma unroll
        for (int o = 4; o; o >>= 1) s += __shfl_xor_sync(0xffffffffu, s, o);
        if (lane == 0) red[0] = s;
    }
    __syncthreads();
    float r = red[0];
    __syncthreads();   // allow reuse of red
    return r;
}

__global__ void __launch_bounds__(256)
ln_res_kernel(const float* __restrict__ res, const float* __restrict__ y,
              const float* __restrict__ g, const float* __restrict__ be,
              float* __restrict__ out)
{
    __shared__ float red[8];
    const int row = blockIdx.x;
    const int t = threadIdx.x;
    const float* yr = y + (size_t)row * CC;

    float v[4];
    float s = 0.0f;
#pragma unroll
    for (int i = 0; i < 4; ++i) { v[i] = yr[t + i * 256]; s += v[i]; }
    const float mean = block_sum(s, red) * (1.0f / CC);

    float sq = 0.0f;
#pragma unroll
    for (int i = 0; i < 4; ++i) { float d = v[i] - mean; sq += d * d; }
    const float var = block_sum(sq, red) * (1.0f / CC);
    const float rstd = rsqrtf(var + 1e-5f);

    const float* rr = res + (size_t)row * CC;
    float* orow = out + (size_t)row * CC;
#pragma unroll
    for (int i = 0; i < 4; ++i) {
        int c = t + i * 256;
        orow[c] = rr[c] + (v[i] - mean) * rstd * g[c] + be[c];
    }
}

// ---------------- launch ----------------
extern "C" void kernel_launch(void* const* d_in, const int* in_sizes, int n_in,
                              void* d_out, int out_size)
{
    const float* x      = (const float*)d_in[0];
    const float* w_attn = (const float*)d_in[1];
    const float* b_attn = (const float*)d_in[2];
    const float* wa1    = (const float*)d_in[3];
    const float* ba1    = (const float*)d_in[4];
    const float* wa2    = (const float*)d_in[5];
    const float* ba2    = (const float*)d_in[6];
    const float* g1     = (const float*)d_in[7];
    const float* be1    = (const float*)d_in[8];
    const float* wf1    = (const float*)d_in[9];
    const float* bf1    = (const float*)d_in[10];
    const float* wf2    = (const float*)d_in[11];
    const float* bf2    = (const float*)d_in[12];
    const float* g2     = (const float*)d_in[13];
    const float* be2    = (const float*)d_in[14];
    float* out = (float*)d_out;

    float *qkv, *att, *h, *x1, *y;
    cudaGetSymbolAddress((void**)&qkv, g_qkv);
    cudaGetSymbolAddress((void**)&att, g_att);
    cudaGetSymbolAddress((void**)&h,   g_h);
    cudaGetSymbolAddress((void**)&x1,  g_x1);
    cudaGetSymbolAddress((void**)&y,   g_y);

    const int att_smem = ATT_SMEM_FLOATS * (int)sizeof(float);
    cudaFuncSetAttribute(attn_kernel, cudaFuncAttributeMaxDynamicSharedMemorySize, att_smem);

    // 1) qkv = x @ w_attn + b_attn           (4096x3072, K=1024)
    gemm_bias_kernel<false><<<dim3(C3 / 128, MTOK / 128), 256>>>(x, w_attn, b_attn, qkv, C3, CC);
    // 2) causal attention -> att (B,T,C)
    attn_kernel<<<dim3(TT / 64, NHH, BB), 256, att_smem>>>(qkv, att);
    // 3) h = gelu(att @ wa1 + ba1)           (4096x4096, K=1024)
    gemm_bias_kernel<true ><<<dim3(C4 / 128, MTOK / 128), 256>>>(att, wa1, ba1, h, C4, CC);
    // 4) y = h @ wa2 + ba2                   (4096x1024, K=4096)
    gemm_bias_kernel<false><<<dim3(CC / 128, MTOK / 128), 256>>>(h, wa2, ba2, y, CC, C4);
    // 5) x1 = x + ln(y)*g1 + be1
    ln_res_kernel<<<MTOK, 256>>>(x, y, g1, be1, x1);
    // 6) h = gelu(x1 @ wf1 + bf1)
    gemm_bias_kernel<true ><<<dim3(C4 / 128, MTOK / 128), 256>>>(x1, wf1, bf1, h, C4, CC);
    // 7) y = h @ wf2 + bf2
    gemm_bias_kernel<false><<<dim3(CC / 128, MTOK / 128), 256>>>(h, wf2, bf2, y, CC, C4);
    // 8) out = x1 + ln(y)*g2 + be2
    ln_res_kernel<<<MTOK, 256>>>(x1, y, g2, be2, out);
}

// round 3
// speedup vs baseline: 2.0655x; 2.0655x over previous
#include <cuda_runtime.h>
#include <cuda_bf16.h>
#include <math.h>
#include <stdint.h>

// Problem dims (fixed)
#define BB 2
#define TT 2048
#define CC 1024
#define NHH 16
#define HDD 64
#define MTOK 4096          // B*T
#define C3 3072
#define C4 4096

// ---------------- scratch (no allocation allowed) ----------------
__device__ float g_qkv[(size_t)MTOK * C3];
__device__ float g_x1 [(size_t)MTOK * CC];
__device__ float g_y  [(size_t)MTOK * CC];

// bf16 split weights, transposed to [N][K]
__device__ __nv_bfloat16 g_wqkv_hi[(size_t)C3 * CC], g_wqkv_lo[(size_t)C3 * CC];
__device__ __nv_bfloat16 g_wa1_hi [(size_t)C4 * CC], g_wa1_lo [(size_t)C4 * CC];
__device__ __nv_bfloat16 g_wa2_hi [(size_t)CC * C4], g_wa2_lo [(size_t)CC * C4];
__device__ __nv_bfloat16 g_wf1_hi [(size_t)C4 * CC], g_wf1_lo [(size_t)C4 * CC];
__device__ __nv_bfloat16 g_wf2_hi [(size_t)CC * C4], g_wf2_lo [(size_t)CC * C4];
// bf16 split activations
__device__ __nv_bfloat16 g_ahi[(size_t)MTOK * CC], g_alo[(size_t)MTOK * CC];   // x / att / x1
__device__ __nv_bfloat16 g_hhi[(size_t)MTOK * C4], g_hlo[(size_t)MTOK * C4];   // gelu outputs

__device__ __forceinline__ float gelu_f(float v) {
    return 0.5f * v * (1.0f + erff(v * 0.7071067811865475f));
}

// ======================= PTX helpers =======================
__device__ __forceinline__ uint32_t smem_u32(const void* p) {
    uint32_t a;
    asm("{ .reg .u64 t; cvta.to.shared.u64 t, %1; cvt.u32.u64 %0, t; }" : "=r"(a) : "l"(p));
    return a;
}
__device__ __forceinline__ void ldsm4(uint32_t* r, uint32_t addr) {
    asm volatile("ldmatrix.sync.aligned.m8n8.x4.shared.b16 {%0,%1,%2,%3}, [%4];"
                 : "=r"(r[0]), "=r"(r[1]), "=r"(r[2]), "=r"(r[3]) : "r"(addr));
}
__device__ __forceinline__ void mma_bf16(float* d, const uint32_t* a, const uint32_t* b) {
    asm volatile(
        "mma.sync.aligned.m16n8k16.row.col.f32.bf16.bf16.f32 "
        "{%0,%1,%2,%3}, {%4,%5,%6,%7}, {%8,%9}, {%0,%1,%2,%3};"
        : "+f"(d[0]), "+f"(d[1]), "+f"(d[2]), "+f"(d[3])
        : "r"(a[0]), "r"(a[1]), "r"(a[2]), "r"(a[3]), "r"(b[0]), "r"(b[1]));
}
__device__ __forceinline__ void cp16(uint32_t dst, const void* src) {
    unsigned long long g = __cvta_generic_to_global(src);
    asm volatile("cp.async.ca.shared.global [%0], [%1], 16;" :: "r"(dst), "l"(g) : "memory");
}
__device__ __forceinline__ void cp_commit() {
    asm volatile("cp.async.commit_group;" ::: "memory");
}
template<int N>
__device__ __forceinline__ void cp_wait() {
    asm volatile("cp.async.wait_group %0;" :: "n"(N) : "memory");
}

// ======================= conversion kernels =======================
__global__ void __launch_bounds__(256)
cvt_act_kernel(const float* __restrict__ in, __nv_bfloat16* __restrict__ hi,
               __nv_bfloat16* __restrict__ lo, int n)
{
    int i = (blockIdx.x * 256 + threadIdx.x) * 4;
    if (i >= n) return;
    float4 v = *(const float4*)(in + i);
    __nv_bfloat16 h0 = __float2bfloat16_rn(v.x), h1 = __float2bfloat16_rn(v.y);
    __nv_bfloat16 h2 = __float2bfloat16_rn(v.z), h3 = __float2bfloat16_rn(v.w);
    __nv_bfloat162 hp0{h0, h1}, hp1{h2, h3};
    __nv_bfloat162 lp0{__float2bfloat16_rn(v.x - __bfloat162float(h0)),
                       __float2bfloat16_rn(v.y - __bfloat162float(h1))};
    __nv_bfloat162 lp1{__float2bfloat16_rn(v.z - __bfloat162float(h2)),
                       __float2bfloat16_rn(v.w - __bfloat162float(h3))};
    *(__nv_bfloat162*)(hi + i)     = hp0;
    *(__nv_bfloat162*)(hi + i + 2) = hp1;
    *(__nv_bfloat162*)(lo + i)     = lp0;
    *(__nv_bfloat162*)(lo + i + 2) = lp1;
}

// W[K][N] fp32 -> hi/lo bf16 [N][K] (transpose + split)
__global__ void __launch_bounds__(256)
cvt_wt_kernel(const float* __restrict__ W, __nv_bfloat16* __restrict__ hi,
              __nv_bfloat16* __restrict__ lo, int K, int N)
{
    __shared__ float tile[32][33];
    const int n0 = blockIdx.x * 32, k0 = blockIdx.y * 32;
    const int tx = threadIdx.x & 31, ty = threadIdx.x >> 5;
#pragma unroll
    for (int r = 0; r < 4; ++r)
        tile[ty + r * 8][tx] = W[(size_t)(k0 + ty + r * 8) * N + n0 + tx];
    __syncthreads();
#pragma unroll
    for (int r = 0; r < 4; ++r) {
        int n = n0 + ty + r * 8;
        float v = tile[tx][ty + r * 8];
        __nv_bfloat16 h = __float2bfloat16_rn(v);
        hi[(size_t)n * K + k0 + tx] = h;
        lo[(size_t)n * K + k0 + tx] = __float2bfloat16_rn(v - __bfloat162float(h));
    }
}

// ======================= HMMA split-bf16 GEMM =======================
// C[M][N] = A[M][K] @ W[K][N] + bias.  A = (Ahi,Alo) [M][K]; W = (Bhi,Blo) [N][K].
// CTA 128x128, BK=32, 8 warps (warp tile 64x32), double-buffered cp.async.
// MODE 0: fp32 out.  MODE 1: exact-GELU, bf16 hi/lo split out.
// smem per stage: Ahi 8K | Alo 8K | Bhi 8K | Blo 8K = 32KB; x2 stages = 64KB.
#define GSMEM 65536
// swizzled smem offset for (row, kq) quadrants of 16B; 64B rows
__device__ __forceinline__ uint32_t sw_off(int row, int kq) {
    return (uint32_t)(row * 64 + (((kq) ^ ((row >> 1) & 3)) << 4));
}

template<int MODE>
__global__ void __launch_bounds__(256)
gemm_mma_kernel(const __nv_bfloat16* __restrict__ Ahi, const __nv_bfloat16* __restrict__ Alo,
                const __nv_bfloat16* __restrict__ Bhi, const __nv_bfloat16* __restrict__ Blo,
                const float* __restrict__ bias, float* __restrict__ Cf,
                __nv_bfloat16* __restrict__ Chi, __nv_bfloat16* __restrict__ Clo,
                int N, int K)
{
    extern __shared__ char smem[];
    const uint32_t sb = smem_u32(smem);

    const int t = threadIdx.x;
    const int wid = t >> 5, lane = t & 31;
    const int bm = blockIdx.y * 128;
    const int bn = blockIdx.x * 128;
    const int wm = wid >> 2, wn = wid & 3;          // 2 x 4 warp grid

    // global->smem mapping: 2048 16B units per stage, 8 per thread
    // unit u: arr = u>>9 (0 Ahi,1 Alo,2 Bhi,3 Blo), row = (u&511)>>2, kq = u&3
    const __nv_bfloat16* gsrc[4] = {Ahi, Alo, Bhi, Blo};

    float acc[4][4][4];
#pragma unroll
    for (int i = 0; i < 4; ++i)
#pragma unroll
        for (int j = 0; j < 4; ++j)
#pragma unroll
            for (int k = 0; k < 4; ++k) acc[i][j][k] = 0.0f;

    const int nc = K >> 5;

    // ldmatrix lane address components
    const int g  = lane >> 3, lr = lane & 7;
    // A: row_in_tile = lr + (g&1)*8 ; kq offset = g>>1
    const int a_rit = lr + (g & 1) * 8, a_kqo = g >> 1;
    // B: row_in_tile = lr + (g>>1)*8 ; kq offset = g&1
    const int b_rit = lr + (g >> 1) * 8, b_kqo = g & 1;

    uint32_t aAhi[4], aAlo[4], aBhi[2], aBlo[2];   // base addrs (row term), per tile
    int aRsw[4], bRsw[2];
#pragma unroll
    for (int mt = 0; mt < 4; ++mt) {
        int row = wm * 64 + mt * 16 + a_rit;
        aAhi[mt] = sb + 0     + row * 64;
        aAlo[mt] = sb + 8192  + row * 64;
        aRsw[mt] = (row >> 1) & 3;
    }
#pragma unroll
    for (int p = 0; p < 2; ++p) {
        int row = wn * 32 + p * 16 + b_rit;
        aBhi[p] = sb + 16384 + row * 64;
        aBlo[p] = sb + 24576 + row * 64;
        bRsw[p] = (row >> 1) & 3;
    }

    // issue loads for chunk c into stage s
    auto issue = [&](int c, int s) {
        const uint32_t st = sb + s * 32768;
        const int kb = c * 32;
#pragma unroll
        for (int i = 0; i < 8; ++i) {
            int u = t + i * 256;
            int arr = u >> 9, v = u & 511, row = v >> 2, kq = v & 3;
            const __nv_bfloat16* src = gsrc[arr] +
                (size_t)((arr < 2 ? bm : bn) + row) * K + kb + kq * 8;
            cp16(st + arr * 8192 + sw_off(row, kq), src);
        }
        cp_commit();
    };

    issue(0, 0);
    for (int c = 0; c < nc; ++c) {
        const int s = c & 1;
        if (c + 1 < nc) { issue(c + 1, s ^ 1); cp_wait<1>(); }
        else            { cp_wait<0>(); }
        __syncthreads();

        const uint32_t stoff = (uint32_t)(s * 32768);
#pragma unroll
        for (int ks = 0; ks < 2; ++ks) {
            uint32_t ah[4][4], al[4][4], bh[4][2], bl[4][2];
#pragma unroll
            for (int mt = 0; mt < 4; ++mt) {
                uint32_t o = (uint32_t)((((2 * ks + a_kqo) ^ aRsw[mt]) << 4));
                ldsm4(ah[mt], aAhi[mt] + stoff + o);
                ldsm4(al[mt], aAlo[mt] + stoff + o);
            }
#pragma unroll
            for (int p = 0; p < 2; ++p) {
                uint32_t r[4];
                uint32_t o = (uint32_t)((((2 * ks + b_kqo) ^ bRsw[p]) << 4));
                ldsm4(r, aBhi[p] + stoff + o);
                bh[2 * p][0] = r[0]; bh[2 * p][1] = r[1];
                bh[2 * p + 1][0] = r[2]; bh[2 * p + 1][1] = r[3];
                ldsm4(r, aBlo[p] + stoff + o);
                bl[2 * p][0] = r[0]; bl[2 * p][1] = r[1];
                bl[2 * p + 1][0] = r[2]; bl[2 * p + 1][1] = r[3];
            }
#pragma unroll
            for (int mt = 0; mt < 4; ++mt)
#pragma unroll
                for (int nt = 0; nt < 4; ++nt) {
                    mma_bf16(acc[mt][nt], ah[mt], bh[nt]);
                    mma_bf16(acc[mt][nt], ah[mt], bl[nt]);
                    mma_bf16(acc[mt][nt], al[mt], bh[nt]);
                }
        }
        __syncthreads();
    }

    // ---------------- epilogue ----------------
    const int mrow = bm + wm * 64;
    const int ncol = bn + wn * 32;
#pragma unroll
    for (int mt = 0; mt < 4; ++mt) {
#pragma unroll
        for (int nt = 0; nt < 4; ++nt) {
            float* d = acc[mt][nt];
            int r0 = mrow + mt * 16 + (lane >> 2);
            int cix = ncol + nt * 8 + (lane & 3) * 2;
            float b0 = bias[cix], b1 = bias[cix + 1];
            float v00 = d[0] + b0, v01 = d[1] + b1;
            float v10 = d[2] + b0, v11 = d[3] + b1;
            if (MODE == 1) {
                v00 = gelu_f(v00); v01 = gelu_f(v01);
                v10 = gelu_f(v10); v11 = gelu_f(v11);
                __nv_bfloat16 h00 = __float2bfloat16_rn(v00), h01 = __float2bfloat16_rn(v01);
                __nv_bfloat16 h10 = __float2bfloat16_rn(v10), h11 = __float2bfloat16_rn(v11);
                __nv_bfloat162 hp0{h00, h01}, hp1{h10, h11};
                __nv_bfloat162 lp0{__float2bfloat16_rn(v00 - __bfloat162float(h00)),
                                   __float2bfloat16_rn(v01 - __bfloat162float(h01))};
                __nv_bfloat162 lp1{__float2bfloat16_rn(v10 - __bfloat162float(h10)),
                                   __float2bfloat16_rn(v11 - __bfloat162float(h11))};
                *(__nv_bfloat162*)&Chi[(size_t)r0 * N + cix]       = hp0;
                *(__nv_bfloat162*)&Clo[(size_t)r0 * N + cix]       = lp0;
                *(__nv_bfloat162*)&Chi[(size_t)(r0 + 8) * N + cix] = hp1;
                *(__nv_bfloat162*)&Clo[(size_t)(r0 + 8) * N + cix] = lp1;
            } else {
                float2 p0{v00, v01}, p1{v10, v11};
                *(float2*)&Cf[(size_t)r0 * N + cix]       = p0;
                *(float2*)&Cf[(size_t)(r0 + 8) * N + cix] = p1;
            }
        }
    }
}

// ---------------- causal attention, fp32, flash-style; writes bf16 split ----
#define ATT_SMEM_FLOATS (4160 + 4160 + 4096 + 192)
__global__ void __launch_bounds__(256)
attn_kernel(const float* __restrict__ qkv,
            __nv_bfloat16* __restrict__ ohi, __nv_bfloat16* __restrict__ olo)
{
    extern __shared__ float sm[];
    float* Qs  = sm;
    float* Ks  = sm + 4160;
    float* Vs  = sm + 8320;
    float* m_s = sm + 12416;
    float* l_s = m_s + 64;
    float* al_s = l_s + 64;

    const int t  = threadIdx.x;
    const int qb = blockIdx.x * 64;
    const int h  = blockIdx.y;
    const int b  = blockIdx.z;

    const float* base = qkv + (size_t)b * TT * C3 + h * HDD;
    const float* Kg = base;
    const float* Qg = base + CC;
    const float* Vg = base + 2 * CC;

    for (int i = t; i < 1024; i += 256) {
        int r = i >> 4, d = (i & 15) * 4;
        float4 q = *(const float4*)&Qg[(size_t)(qb + r) * C3 + d];
        Qs[(d + 0) * 65 + r] = q.x;
        Qs[(d + 1) * 65 + r] = q.y;
        Qs[(d + 2) * 65 + r] = q.z;
        Qs[(d + 3) * 65 + r] = q.w;
    }
    if (t < 64) { m_s[t] = -1e30f; l_s[t] = 0.0f; }

    const int tr = t >> 4, tc = t & 15;
    const int r0 = tr * 4, c0 = tc * 4;

    float O[4][4];
#pragma unroll
    for (int i = 0; i < 4; ++i)
#pragma unroll
        for (int j = 0; j < 4; ++j) O[i][j] = 0.0f;

    const int ntiles = blockIdx.x + 1;
    for (int kt = 0; kt < ntiles; ++kt) {
        const int kb = kt * 64;
        __syncthreads();
        for (int i = t; i < 1024; i += 256) {
            int c = i >> 4, d = (i & 15) * 4;
            float4 kv = *(const float4*)&Kg[(size_t)(kb + c) * C3 + d];
            Ks[(d + 0) * 65 + c] = kv.x;
            Ks[(d + 1) * 65 + c] = kv.y;
            Ks[(d + 2) * 65 + c] = kv.z;
            Ks[(d + 3) * 65 + c] = kv.w;
            *(float4*)&Vs[c * 64 + d] = *(const float4*)&Vg[(size_t)(kb + c) * C3 + d];
        }
        __syncthreads();

        float S[4][4];
#pragma unroll
        for (int i = 0; i < 4; ++i)
#pragma unroll
            for (int j = 0; j < 4; ++j) S[i][j] = 0.0f;
#pragma unroll 4
        for (int d = 0; d < 64; ++d) {
            float qv[4], kv[4];
#pragma unroll
            for (int i = 0; i < 4; ++i) qv[i] = Qs[d * 65 + r0 + i];
#pragma unroll
            for (int j = 0; j < 4; ++j) kv[j] = Ks[d * 65 + c0 + j];
#pragma unroll
            for (int i = 0; i < 4; ++i)
#pragma unroll
                for (int j = 0; j < 4; ++j) S[i][j] += qv[i] * kv[j];
        }
        __syncthreads();

#pragma unroll
        for (int i = 0; i < 4; ++i) {
            int q = qb + r0 + i;
#pragma unroll
            for (int j = 0; j < 4; ++j) {
                int k = kb + c0 + j;
                Ks[(r0 + i) * 65 + c0 + j] = (k <= q) ? S[i][j] * 0.125f : -1e30f;
            }
        }
        __syncthreads();

        if (t < 64) {
            const int r = t;
            float mo = m_s[r];
            float rowmax = -1e30f;
            for (int c = 0; c < 64; ++c) rowmax = fmaxf(rowmax, Ks[r * 65 + c]);
            float mn = fmaxf(mo, rowmax);
            float a  = __expf(mo - mn);
            float s  = 0.0f;
            for (int c = 0; c < 64; ++c) {
                float p = __expf(Ks[r * 65 + c] - mn);
                Ks[r * 65 + c] = p;
                s += p;
            }
            l_s[r]  = l_s[r] * a + s;
            m_s[r]  = mn;
            al_s[r] = a;
        }
        __syncthreads();

        float al[4];
#pragma unroll
        for (int i = 0; i < 4; ++i) al[i] = al_s[r0 + i];
#pragma unroll
        for (int i = 0; i < 4; ++i)
#pragma unroll
            for (int j = 0; j < 4; ++j) O[i][j] *= al[i];
#pragma unroll 4
        for (int k = 0; k < 64; ++k) {
            float pv[4];
#pragma unroll
            for (int i = 0; i < 4; ++i) pv[i] = Ks[(r0 + i) * 65 + k];
            float4 vv = *(const float4*)&Vs[k * 64 + c0];
#pragma unroll
            for (int i = 0; i < 4; ++i) {
                O[i][0] += pv[i] * vv.x;
                O[i][1] += pv[i] * vv.y;
                O[i][2] += pv[i] * vv.z;
                O[i][3] += pv[i] * vv.w;
            }
        }
    }

#pragma unroll
    for (int i = 0; i < 4; ++i) {
        int r = r0 + i;
        float inv = 1.0f / l_s[r];
        size_t idx = ((size_t)b * TT + qb + r) * CC + h * HDD + c0;
        float v0 = O[i][0] * inv, v1 = O[i][1] * inv;
        float v2 = O[i][2] * inv, v3 = O[i][3] * inv;
        __nv_bfloat16 h0 = __float2bfloat16_rn(v0), h1 = __float2bfloat16_rn(v1);
        __nv_bfloat16 h2 = __float2bfloat16_rn(v2), h3 = __float2bfloat16_rn(v3);
        __nv_bfloat162 hp0{h0, h1}, hp1{h2, h3};
        __nv_bfloat162 lp0{__float2bfloat16_rn(v0 - __bfloat162float(h0)),
                           __float2bfloat16_rn(v1 - __bfloat162float(h1))};
        __nv_bfloat162 lp1{__float2bfloat16_rn(v2 - __bfloat162float(h2)),
                           __float2bfloat16_rn(v3 - __bfloat162float(h3))};
        *(__nv_bfloat162*)&ohi[idx]     = hp0;
        *(__nv_bfloat162*)&ohi[idx + 2] = hp1;
        *(__nv_bfloat162*)&olo[idx]     = lp0;
        *(__nv_bfloat162*)&olo[idx + 2] = lp1;
    }
}

// ---------------- LayerNorm + residual (optional bf16-split extra output) ---
__device__ __forceinline__ float block_sum(float v, float* red) {
    const int lane = threadIdx.x & 31, w = threadIdx.x >> 5;
#pragma unroll
    for (int o = 16; o; o >>= 1) v += __shfl_xor_sync(0xffffffffu, v, o);
    if (lane == 0) red[w] = v;
    __syncthreads();
    if (w == 0) {
        float s = (lane < 8) ? red[lane] : 0.0f;
#pragma unroll
        for (int o = 4; o; o >>= 1) s += __shfl_xor_sync(0xffffffffu, s, o);
        if (lane == 0) red[0] = s;
    }
    __syncthreads();
    float r = red[0];
    __syncthreads();
    return r;
}

template<bool SPLIT>
__global__ void __launch_bounds__(256)
ln_res_kernel(const float* __restrict__ res, const float* __restrict__ y,
              const float* __restrict__ g, const float* __restrict__ be,
              float* __restrict__ out,
              __nv_bfloat16* __restrict__ ohi, __nv_bfloat16* __restrict__ olo)
{
    __shared__ float red[8];
    const int row = blockIdx.x;
    const int t = threadIdx.x;
    const float* yr = y + (size_t)row * CC;

    float v[4];
    float s = 0.0f;
#pragma unroll
    for (int i = 0; i < 4; ++i) { v[i] = yr[t + i * 256]; s += v[i]; }
    const float mean = block_sum(s, red) * (1.0f / CC);

    float sq = 0.0f;
#pragma unroll
    for (int i = 0; i < 4; ++i) { float d = v[i] - mean; sq += d * d; }
    const float var = block_sum(sq, red) * (1.0f / CC);
    const float rstd = rsqrtf(var + 1e-5f);

    const float* rr = res + (size_t)row * CC;
    float* orow = out + (size_t)row * CC;
#pragma unroll
    for (int i = 0; i < 4; ++i) {
        int c = t + i * 256;
        float o = rr[c] + (v[i] - mean) * rstd * g[c] + be[c];
        orow[c] = o;
        if (SPLIT) {
            __nv_bfloat16 h = __float2bfloat16_rn(o);
            ohi[(size_t)row * CC + c] = h;
            olo[(size_t)row * CC + c] = __float2bfloat16_rn(o - __bfloat162float(h));
        }
    }
}

// ---------------- launch ----------------
extern "C" void kernel_launch(void* const* d_in, const int* in_sizes, int n_in,
                              void* d_out, int out_size)
{
    const float* x      = (const float*)d_in[0];
    const float* w_attn = (const float*)d_in[1];
    const float* b_attn = (const float*)d_in[2];
    const float* wa1    = (const float*)d_in[3];
    const float* ba1    = (const float*)d_in[4];
    const float* wa2    = (const float*)d_in[5];
    const float* ba2    = (const float*)d_in[6];
    const float* g1     = (const float*)d_in[7];
    const float* be1    = (const float*)d_in[8];
    const float* wf1    = (const float*)d_in[9];
    const float* bf1    = (const float*)d_in[10];
    const float* wf2    = (const float*)d_in[11];
    const float* bf2    = (const float*)d_in[12];
    const float* g2     = (const float*)d_in[13];
    const float* be2    = (const float*)d_in[14];
    float* out = (float*)d_out;

    float *qkv, *x1, *y;
    cudaGetSymbolAddress((void**)&qkv, g_qkv);
    cudaGetSymbolAddress((void**)&x1,  g_x1);
    cudaGetSymbolAddress((void**)&y,   g_y);

    __nv_bfloat16 *wqkv_hi, *wqkv_lo, *wa1_hi, *wa1_lo, *wa2_hi, *wa2_lo,
                  *wf1_hi, *wf1_lo, *wf2_hi, *wf2_lo, *ahi, *alo, *hhi, *hlo;
    cudaGetSymbolAddress((void**)&wqkv_hi, g_wqkv_hi);
    cudaGetSymbolAddress((void**)&wqkv_lo, g_wqkv_lo);
    cudaGetSymbolAddress((void**)&wa1_hi,  g_wa1_hi);
    cudaGetSymbolAddress((void**)&wa1_lo,  g_wa1_lo);
    cudaGetSymbolAddress((void**)&wa2_hi,  g_wa2_hi);
    cudaGetSymbolAddress((void**)&wa2_lo,  g_wa2_lo);
    cudaGetSymbolAddress((void**)&wf1_hi,  g_wf1_hi);
    cudaGetSymbolAddress((void**)&wf1_lo,  g_wf1_lo);
    cudaGetSymbolAddress((void**)&wf2_hi,  g_wf2_hi);
    cudaGetSymbolAddress((void**)&wf2_lo,  g_wf2_lo);
    cudaGetSymbolAddress((void**)&ahi,     g_ahi);
    cudaGetSymbolAddress((void**)&alo,     g_alo);
    cudaGetSymbolAddress((void**)&hhi,     g_hhi);
    cudaGetSymbolAddress((void**)&hlo,     g_hlo);

    const int att_smem = ATT_SMEM_FLOATS * (int)sizeof(float);
    cudaFuncSetAttribute(attn_kernel, cudaFuncAttributeMaxDynamicSharedMemorySize, att_smem);
    cudaFuncSetAttribute(gemm_mma_kernel<0>, cudaFuncAttributeMaxDynamicSharedMemorySize, GSMEM);
    cudaFuncSetAttribute(gemm_mma_kernel<1>, cudaFuncAttributeMaxDynamicSharedMemorySize, GSMEM);

    // weight transpose + bf16 split
    cvt_wt_kernel<<<dim3(C3 / 32, CC / 32), 256>>>(w_attn, wqkv_hi, wqkv_lo, CC, C3);
    cvt_wt_kernel<<<dim3(C4 / 32, CC / 32), 256>>>(wa1, wa1_hi, wa1_lo, CC, C4);
    cvt_wt_kernel<<<dim3(CC / 32, C4 / 32), 256>>>(wa2, wa2_hi, wa2_lo, C4, CC);
    cvt_wt_kernel<<<dim3(C4 / 32, CC / 32), 256>>>(wf1, wf1_hi, wf1_lo, CC, C4);
    cvt_wt_kernel<<<dim3(CC / 32, C4 / 32), 256>>>(wf2, wf2_hi, wf2_lo, C4, CC);

    // 1) qkv = x @ w_attn + b_attn
    cvt_act_kernel<<<(MTOK * CC) / 1024, 256>>>(x, ahi, alo, MTOK * CC);
    gemm_mma_kernel<0><<<dim3(C3 / 128, MTOK / 128), 256, GSMEM>>>(
        ahi, alo, wqkv_hi, wqkv_lo, b_attn, qkv, nullptr, nullptr, C3, CC);
    // 2) attention -> split bf16 att (reuse ahi/alo)
    attn_kernel<<<dim3(TT / 64, NHH, BB), 256, att_smem>>>(qkv, ahi, alo);
    // 3) h = gelu(att @ wa1 + ba1) -> split bf16
    gemm_mma_kernel<1><<<dim3(C4 / 128, MTOK / 128), 256, GSMEM>>>(
        ahi, alo, wa1_hi, wa1_lo, ba1, nullptr, hhi, hlo, C4, CC);
    // 4) y = h @ wa2 + ba2
    gemm_mma_kernel<0><<<dim3(CC / 128, MTOK / 128), 256, GSMEM>>>(
        hhi, hlo, wa2_hi, wa2_lo, ba2, y, nullptr, nullptr, CC, C4);
    // 5) x1 = x + ln(y); also emit split bf16 x1
    ln_res_kernel<true><<<MTOK, 256>>>(x, y, g1, be1, x1, ahi, alo);
    // 6) h = gelu(x1 @ wf1 + bf1) -> split bf16
    gemm_mma_kernel<1><<<dim3(C4 / 128, MTOK / 128), 256, GSMEM>>>(
        ahi, alo, wf1_hi, wf1_lo, bf1, nullptr, hhi, hlo, C4, CC);
    // 7) y = h @ wf2 + bf2
    gemm_mma_kernel<0><<<dim3(CC / 128, MTOK / 128), 256, GSMEM>>>(
        hhi, hlo, wf2_hi, wf2_lo, bf2, y, nullptr, nullptr, CC, C4);
    // 8) out = x1 + ln(y)
    ln_res_kernel<false><<<MTOK, 256>>>(x1, y, g2, be2, out, nullptr, nullptr);
}

// round 4
// speedup vs baseline: 2.6525x; 1.2842x over previous
#include <cuda_runtime.h>
#include <cuda_bf16.h>
#include <math.h>
#include <stdint.h>

// Problem dims (fixed)
#define BB 2
#define TT 2048
#define CC 1024
#define NHH 16
#define HDD 64
#define MTOK 4096          // B*T
#define C3 3072
#define C4 4096

// ---------------- scratch (no allocation allowed) ----------------
__device__ float g_x1 [(size_t)MTOK * CC];
__device__ float g_y  [(size_t)MTOK * CC];

// bf16 split weights, transposed to [N][K]
__device__ __nv_bfloat16 g_wqkv_hi[(size_t)C3 * CC], g_wqkv_lo[(size_t)C3 * CC];
__device__ __nv_bfloat16 g_wa1_hi [(size_t)C4 * CC], g_wa1_lo [(size_t)C4 * CC];
__device__ __nv_bfloat16 g_wa2_hi [(size_t)CC * C4], g_wa2_lo [(size_t)CC * C4];
__device__ __nv_bfloat16 g_wf1_hi [(size_t)C4 * CC], g_wf1_lo [(size_t)C4 * CC];
__device__ __nv_bfloat16 g_wf2_hi [(size_t)CC * C4], g_wf2_lo [(size_t)CC * C4];
// bf16 split activations
__device__ __nv_bfloat16 g_ahi [(size_t)MTOK * CC], g_alo [(size_t)MTOK * CC];
__device__ __nv_bfloat16 g_hhi [(size_t)MTOK * C4], g_hlo [(size_t)MTOK * C4];
__device__ __nv_bfloat16 g_qkvh[(size_t)MTOK * C3], g_qkvl[(size_t)MTOK * C3];

__device__ __forceinline__ float gelu_f(float v) {
    return 0.5f * v * (1.0f + erff(v * 0.7071067811865475f));
}

// ======================= PTX helpers =======================
__device__ __forceinline__ uint32_t smem_u32(const void* p) {
    uint32_t a;
    asm("{ .reg .u64 t; cvta.to.shared.u64 t, %1; cvt.u32.u64 %0, t; }" : "=r"(a) : "l"(p));
    return a;
}
__device__ __forceinline__ void ldsm4(uint32_t* r, uint32_t addr) {
    asm volatile("ldmatrix.sync.aligned.m8n8.x4.shared.b16 {%0,%1,%2,%3}, [%4];"
                 : "=r"(r[0]), "=r"(r[1]), "=r"(r[2]), "=r"(r[3]) : "r"(addr));
}
__device__ __forceinline__ void ldsm4t(uint32_t* r, uint32_t addr) {
    asm volatile("ldmatrix.sync.aligned.m8n8.x4.trans.shared.b16 {%0,%1,%2,%3}, [%4];"
                 : "=r"(r[0]), "=r"(r[1]), "=r"(r[2]), "=r"(r[3]) : "r"(addr));
}
__device__ __forceinline__ void mma_bf16(float* d, const uint32_t* a, const uint32_t* b) {
    asm volatile(
        "mma.sync.aligned.m16n8k16.row.col.f32.bf16.bf16.f32 "
        "{%0,%1,%2,%3}, {%4,%5,%6,%7}, {%8,%9}, {%0,%1,%2,%3};"
        : "+f"(d[0]), "+f"(d[1]), "+f"(d[2]), "+f"(d[3])
        : "r"(a[0]), "r"(a[1]), "r"(a[2]), "r"(a[3]), "r"(b[0]), "r"(b[1]));
}
__device__ __forceinline__ void cp16(uint32_t dst, const void* src) {
    unsigned long long g = __cvta_generic_to_global(src);
    asm volatile("cp.async.ca.shared.global [%0], [%1], 16;" :: "r"(dst), "l"(g) : "memory");
}
__device__ __forceinline__ void cp_commit() {
    asm volatile("cp.async.commit_group;" ::: "memory");
}
template<int N>
__device__ __forceinline__ void cp_wait() {
    asm volatile("cp.async.wait_group %0;" :: "n"(N) : "memory");
}
// split two floats into packed bf16x2 hi and lo
__device__ __forceinline__ void split2(float a, float b, uint32_t& hi, uint32_t& lo) {
    __nv_bfloat16 ha = __float2bfloat16_rn(a), hb = __float2bfloat16_rn(b);
    __nv_bfloat162 H{ha, hb};
    __nv_bfloat162 L{__float2bfloat16_rn(a - __bfloat162float(ha)),
                     __float2bfloat16_rn(b - __bfloat162float(hb))};
    hi = *(uint32_t*)&H;
    lo = *(uint32_t*)&L;
}

// ======================= conversion kernels =======================
__global__ void __launch_bounds__(256)
cvt_act_kernel(const float* __restrict__ in, __nv_bfloat16* __restrict__ hi,
               __nv_bfloat16* __restrict__ lo, int n)
{
    int i = (blockIdx.x * 256 + threadIdx.x) * 4;
    if (i >= n) return;
    float4 v = *(const float4*)(in + i);
    uint32_t h0, l0, h1, l1;
    split2(v.x, v.y, h0, l0);
    split2(v.z, v.w, h1, l1);
    *(uint32_t*)(hi + i)     = h0;
    *(uint32_t*)(hi + i + 2) = h1;
    *(uint32_t*)(lo + i)     = l0;
    *(uint32_t*)(lo + i + 2) = l1;
}

// W[K][N] fp32 -> hi/lo bf16 [N][K] (transpose + split)
__global__ void __launch_bounds__(256)
cvt_wt_kernel(const float* __restrict__ W, __nv_bfloat16* __restrict__ hi,
              __nv_bfloat16* __restrict__ lo, int K, int N)
{
    __shared__ float tile[32][33];
    const int n0 = blockIdx.x * 32, k0 = blockIdx.y * 32;
    const int tx = threadIdx.x & 31, ty = threadIdx.x >> 5;
#pragma unroll
    for (int r = 0; r < 4; ++r)
        tile[ty + r * 8][tx] = W[(size_t)(k0 + ty + r * 8) * N + n0 + tx];
    __syncthreads();
#pragma unroll
    for (int r = 0; r < 4; ++r) {
        int n = n0 + ty + r * 8;
        float v = tile[tx][ty + r * 8];
        __nv_bfloat16 h = __float2bfloat16_rn(v);
        hi[(size_t)n * K + k0 + tx] = h;
        lo[(size_t)n * K + k0 + tx] = __float2bfloat16_rn(v - __bfloat162float(h));
    }
}

// ======================= HMMA split-bf16 GEMM =======================
// CTA 128x128, BK=32, 8 warps (warp tile 64x32), 3-stage cp.async pipeline.
// MODE 0: fp32 out.  MODE 1: exact-GELU + bf16 split out.  MODE 2: bf16 split out.
#define GSMEM (3 * 32768)
__device__ __forceinline__ uint32_t sw_off(int row, int kq) {
    return (uint32_t)(row * 64 + (((kq) ^ ((row >> 1) & 3)) << 4));
}

template<int MODE>
__global__ void __launch_bounds__(256)
gemm_mma_kernel(const __nv_bfloat16* __restrict__ Ahi, const __nv_bfloat16* __restrict__ Alo,
                const __nv_bfloat16* __restrict__ Bhi, const __nv_bfloat16* __restrict__ Blo,
                const float* __restrict__ bias, float* __restrict__ Cf,
                __nv_bfloat16* __restrict__ Chi, __nv_bfloat16* __restrict__ Clo,
                int N, int K)
{
    extern __shared__ char smem[];
    const uint32_t sb = smem_u32(smem);

    const int t = threadIdx.x;
    const int wid = t >> 5, lane = t & 31;
    const int bm = blockIdx.y * 128;
    const int bn = blockIdx.x * 128;
    const int wm = wid >> 2, wn = wid & 3;

    const __nv_bfloat16* gsrc[4] = {Ahi, Alo, Bhi, Blo};

    float acc[4][4][4];
#pragma unroll
    for (int i = 0; i < 4; ++i)
#pragma unroll
        for (int j = 0; j < 4; ++j)
#pragma unroll
            for (int k = 0; k < 4; ++k) acc[i][j][k] = 0.0f;

    const int nc = K >> 5;

    const int g  = lane >> 3, lr = lane & 7;
    const int a_rit = lr + (g & 1) * 8, a_kqo = g >> 1;
    const int b_rit = lr + (g >> 1) * 8, b_kqo = g & 1;

    uint32_t aAhi[4], aAlo[4], aBhi[2], aBlo[2];
    int aRsw[4], bRsw[2];
#pragma unroll
    for (int mt = 0; mt < 4; ++mt) {
        int row = wm * 64 + mt * 16 + a_rit;
        aAhi[mt] = sb + 0     + row * 64;
        aAlo[mt] = sb + 8192  + row * 64;
        aRsw[mt] = (row >> 1) & 3;
    }
#pragma unroll
    for (int p = 0; p < 2; ++p) {
        int row = wn * 32 + p * 16 + b_rit;
        aBhi[p] = sb + 16384 + row * 64;
        aBlo[p] = sb + 24576 + row * 64;
        bRsw[p] = (row >> 1) & 3;
    }

    auto issue = [&](int c, int s) {
        const uint32_t st = sb + s * 32768;
        const int kb = c * 32;
#pragma unroll
        for (int i = 0; i < 8; ++i) {
            int u = t + i * 256;
            int arr = u >> 9, v = u & 511, row = v >> 2, kq = v & 3;
            const __nv_bfloat16* src = gsrc[arr] +
                (size_t)((arr < 2 ? bm : bn) + row) * K + kb + kq * 8;
            cp16(st + arr * 8192 + sw_off(row, kq), src);
        }
        cp_commit();
    };

    issue(0, 0);
    issue(1, 1);
    int s = 0;
    for (int c = 0; c < nc; ++c) {
        if (c + 2 < nc) { issue(c + 2, (c + 2) % 3); cp_wait<2>(); }
        else if (c + 1 < nc) cp_wait<1>();
        else cp_wait<0>();
        __syncthreads();

        const uint32_t stoff = (uint32_t)(s * 32768);
#pragma unroll
        for (int ks = 0; ks < 2; ++ks) {
            uint32_t ah[4][4], al[4][4], bh[4][2], bl[4][2];
#pragma unroll
            for (int mt = 0; mt < 4; ++mt) {
                uint32_t o = (uint32_t)((((2 * ks + a_kqo) ^ aRsw[mt]) << 4));
                ldsm4(ah[mt], aAhi[mt] + stoff + o);
                ldsm4(al[mt], aAlo[mt] + stoff + o);
            }
#pragma unroll
            for (int p = 0; p < 2; ++p) {
                uint32_t r[4];
                uint32_t o = (uint32_t)((((2 * ks + b_kqo) ^ bRsw[p]) << 4));
                ldsm4(r, aBhi[p] + stoff + o);
                bh[2 * p][0] = r[0]; bh[2 * p][1] = r[1];
                bh[2 * p + 1][0] = r[2]; bh[2 * p + 1][1] = r[3];
                ldsm4(r, aBlo[p] + stoff + o);
                bl[2 * p][0] = r[0]; bl[2 * p][1] = r[1];
                bl[2 * p + 1][0] = r[2]; bl[2 * p + 1][1] = r[3];
            }
#pragma unroll
            for (int mt = 0; mt < 4; ++mt)
#pragma unroll
                for (int nt = 0; nt < 4; ++nt) {
                    mma_bf16(acc[mt][nt], ah[mt], bh[nt]);
                    mma_bf16(acc[mt][nt], ah[mt], bl[nt]);
                    mma_bf16(acc[mt][nt], al[mt], bh[nt]);
                }
        }
        __syncthreads();
        s = (s + 1) % 3;
    }

    // ---------------- epilogue ----------------
    const int mrow = bm + wm * 64;
    const int ncol = bn + wn * 32;
#pragma unroll
    for (int mt = 0; mt < 4; ++mt) {
#pragma unroll
        for (int nt = 0; nt < 4; ++nt) {
            float* d = acc[mt][nt];
            int r0 = mrow + mt * 16 + (lane >> 2);
            int cix = ncol + nt * 8 + (lane & 3) * 2;
            float b0 = bias[cix], b1 = bias[cix + 1];
            float v00 = d[0] + b0, v01 = d[1] + b1;
            float v10 = d[2] + b0, v11 = d[3] + b1;
            if (MODE == 0) {
                float2 p0{v00, v01}, p1{v10, v11};
                *(float2*)&Cf[(size_t)r0 * N + cix]       = p0;
                *(float2*)&Cf[(size_t)(r0 + 8) * N + cix] = p1;
            } else {
                if (MODE == 1) {
                    v00 = gelu_f(v00); v01 = gelu_f(v01);
                    v10 = gelu_f(v10); v11 = gelu_f(v11);
                }
                uint32_t h0, l0, h1, l1;
                split2(v00, v01, h0, l0);
                split2(v10, v11, h1, l1);
                *(uint32_t*)&Chi[(size_t)r0 * N + cix]       = h0;
                *(uint32_t*)&Clo[(size_t)r0 * N + cix]       = l0;
                *(uint32_t*)&Chi[(size_t)(r0 + 8) * N + cix] = h1;
                *(uint32_t*)&Clo[(size_t)(r0 + 8) * N + cix] = l1;
            }
        }
    }
}

// ======================= HMMA causal attention (FA2-style) =======================
// grid (T/64, NH, B), 128 threads (4 warps x 16 query rows).
// qkv split bf16: [tok][3C], order K|Q|V, head h at col h*64.
// smem: Qh Ql Kh Kl Vh Vl, 64x64 bf16 each, 128B rows, 8-way xor swizzle. 48KB.
#define ASMEM 49152
__device__ __forceinline__ uint32_t asw(int row, int u) {
    return (uint32_t)(row * 128 + ((u ^ (row & 7)) << 4));
}

__global__ void __launch_bounds__(128, 3)
attn_mma_kernel(const __nv_bfloat16* __restrict__ qkvh, const __nv_bfloat16* __restrict__ qkvl,
                __nv_bfloat16* __restrict__ ohi, __nv_bfloat16* __restrict__ olo)
{
    extern __shared__ char asmem[];
    const uint32_t sb = smem_u32(asmem);

    const int t = threadIdx.x, wid = t >> 5, lane = t & 31;
    const int qb = blockIdx.x * 64;
    const int h  = blockIdx.y, b = blockIdx.z;

    const __nv_bfloat16* Kh_g = qkvh + (size_t)b * TT * C3 + h * HDD;
    const __nv_bfloat16* Kl_g = qkvl + (size_t)b * TT * C3 + h * HDD;
    const __nv_bfloat16* Qh_g = Kh_g + CC;
    const __nv_bfloat16* Ql_g = Kl_g + CC;
    const __nv_bfloat16* Vh_g = Kh_g + 2 * CC;
    const __nv_bfloat16* Vl_g = Kl_g + 2 * CC;

    // load Q (both arrays): 1024 16B-units
#pragma unroll
    for (int i = 0; i < 8; ++i) {
        int uu = t + i * 128;
        int arr = uu >> 9, v = uu & 511, row = v >> 3, u = v & 7;
        const __nv_bfloat16* src = (arr ? Ql_g : Qh_g) + (size_t)(qb + row) * C3 + u * 8;
        cp16(sb + arr * 8192 + asw(row, u), src);
    }
    cp_commit();

    const int g = lane >> 3, lr = lane & 7;
    const int r = lane >> 2, c = lane & 3;
    // A (Q) ldmatrix row
    const int qrow = wid * 16 + lr + ((g & 1) << 3);
    const int a_u  = g >> 1;
    // B (K) ldmatrix rows (per p)
    const int krit = lr + ((g >> 1) << 3);
    const int b_u  = g & 1;
    // B (V, trans) rows
    const int vrit = lr + ((g & 1) << 3);
    const int v_u  = g >> 1;

    float O[8][4];
#pragma unroll
    for (int i = 0; i < 8; ++i)
#pragma unroll
        for (int j = 0; j < 4; ++j) O[i][j] = 0.0f;
    float m0 = -1e30f, m1 = -1e30f, l0 = 0.0f, l1 = 0.0f;

    const int ntiles = blockIdx.x + 1;
    for (int kt = 0; kt < ntiles; ++kt) {
        const int kb = kt * 64;
        __syncthreads();   // prior tile's reads complete
#pragma unroll
        for (int i = 0; i < 16; ++i) {
            int uu = t + i * 128;
            int arr = uu >> 9, v = uu & 511, row = v >> 3, u = v & 7;
            const __nv_bfloat16* src;
            if      (arr == 0) src = Kh_g + (size_t)(kb + row) * C3 + u * 8;
            else if (arr == 1) src = Kl_g + (size_t)(kb + row) * C3 + u * 8;
            else if (arr == 2) src = Vh_g + (size_t)(kb + row) * C3 + u * 8;
            else               src = Vl_g + (size_t)(kb + row) * C3 + u * 8;
            cp16(sb + 16384 + arr * 8192 + asw(row, u), src);
        }
        cp_commit();
        cp_wait<0>();
        __syncthreads();

        // ---- S = Q K^T (split, 3 passes) ----
        float S[8][4];
#pragma unroll
        for (int i = 0; i < 8; ++i)
#pragma unroll
            for (int j = 0; j < 4; ++j) S[i][j] = 0.0f;

#pragma unroll
        for (int kk = 0; kk < 4; ++kk) {
            uint32_t ah[4], al[4];
            uint32_t aoq = (uint32_t)(qrow * 128 + ((((kk << 1) | a_u) ^ (qrow & 7)) << 4));
            ldsm4(ah, sb + aoq);
            ldsm4(al, sb + 8192 + aoq);
#pragma unroll
            for (int p = 0; p < 4; ++p) {
                int krow = (p << 4) + krit;
                uint32_t ko = (uint32_t)(krow * 128 + ((((kk << 1) | b_u) ^ (krow & 7)) << 4));
                uint32_t bh[4], bl[4];
                ldsm4(bh, sb + 16384 + ko);
                ldsm4(bl, sb + 24576 + ko);
                mma_bf16(S[2 * p],     ah, bh);
                mma_bf16(S[2 * p],     ah, bl);
                mma_bf16(S[2 * p],     al, bh);
                mma_bf16(S[2 * p + 1], ah, bh + 2);
                mma_bf16(S[2 * p + 1], ah, bl + 2);
                mma_bf16(S[2 * p + 1], al, bh + 2);
            }
        }

        // scale + mask
#pragma unroll
        for (int nt = 0; nt < 8; ++nt)
#pragma unroll
            for (int e = 0; e < 4; ++e) S[nt][e] *= 0.125f;
        if (kt == blockIdx.x) {
            const int q0 = qb + wid * 16 + r, q1 = q0 + 8;
#pragma unroll
            for (int nt = 0; nt < 8; ++nt) {
                int k0 = kb + 8 * nt + 2 * c;
                if (k0     > q0) S[nt][0] = -1e30f;
                if (k0 + 1 > q0) S[nt][1] = -1e30f;
                if (k0     > q1) S[nt][2] = -1e30f;
                if (k0 + 1 > q1) S[nt][3] = -1e30f;
            }
        }

        // ---- online softmax (register) ----
        float mx0 = -1e30f, mx1 = -1e30f;
#pragma unroll
        for (int nt = 0; nt < 8; ++nt) {
            mx0 = fmaxf(mx0, fmaxf(S[nt][0], S[nt][1]));
            mx1 = fmaxf(mx1, fmaxf(S[nt][2], S[nt][3]));
        }
        mx0 = fmaxf(mx0, __shfl_xor_sync(0xffffffffu, mx0, 1));
        mx0 = fmaxf(mx0, __shfl_xor_sync(0xffffffffu, mx0, 2));
        mx1 = fmaxf(mx1, __shfl_xor_sync(0xffffffffu, mx1, 1));
        mx1 = fmaxf(mx1, __shfl_xor_sync(0xffffffffu, mx1, 2));
        float mn0 = fmaxf(m0, mx0), mn1 = fmaxf(m1, mx1);
        float al0 = __expf(m0 - mn0), al1 = __expf(m1 - mn1);
        m0 = mn0; m1 = mn1;

        float s0 = 0.0f, s1 = 0.0f;
#pragma unroll
        for (int nt = 0; nt < 8; ++nt) {
            S[nt][0] = __expf(S[nt][0] - mn0);
            S[nt][1] = __expf(S[nt][1] - mn0);
            S[nt][2] = __expf(S[nt][2] - mn1);
            S[nt][3] = __expf(S[nt][3] - mn1);
            s0 += S[nt][0] + S[nt][1];
            s1 += S[nt][2] + S[nt][3];
        }
        l0 = l0 * al0 + s0;
        l1 = l1 * al1 + s1;
#pragma unroll
        for (int nt = 0; nt < 8; ++nt) {
            O[nt][0] *= al0; O[nt][1] *= al0;
            O[nt][2] *= al1; O[nt][3] *= al1;
        }

        // ---- O += P V (split, 3 passes), P frags built in-register ----
#pragma unroll
        for (int kk = 0; kk < 4; ++kk) {
            uint32_t ph[4], pl[4];
            split2(S[2 * kk][0],     S[2 * kk][1],     ph[0], pl[0]);
            split2(S[2 * kk][2],     S[2 * kk][3],     ph[1], pl[1]);
            split2(S[2 * kk + 1][0], S[2 * kk + 1][1], ph[2], pl[2]);
            split2(S[2 * kk + 1][2], S[2 * kk + 1][3], ph[3], pl[3]);
            int vrow = (kk << 4) + vrit;
#pragma unroll
            for (int p = 0; p < 4; ++p) {
                uint32_t vo = (uint32_t)(vrow * 128 + ((((p << 1) | v_u) ^ (vrow & 7)) << 4));
                uint32_t vh[4], vl[4];
                ldsm4t(vh, sb + 32768 + vo);
                ldsm4t(vl, sb + 40960 + vo);
                mma_bf16(O[2 * p],     ph, vh);
                mma_bf16(O[2 * p],     ph, vl);
                mma_bf16(O[2 * p],     pl, vh);
                mma_bf16(O[2 * p + 1], ph, vh + 2);
                mma_bf16(O[2 * p + 1], ph, vl + 2);
                mma_bf16(O[2 * p + 1], pl, vh + 2);
            }
        }
    }

    // final l reduction across quad + write split bf16
    l0 += __shfl_xor_sync(0xffffffffu, l0, 1);
    l0 += __shfl_xor_sync(0xffffffffu, l0, 2);
    l1 += __shfl_xor_sync(0xffffffffu, l1, 1);
    l1 += __shfl_xor_sync(0xffffffffu, l1, 2);
    const float i0 = 1.0f / l0, i1 = 1.0f / l1;
    const int row0 = qb + wid * 16 + r, row1 = row0 + 8;
#pragma unroll
    for (int nt = 0; nt < 8; ++nt) {
        int col = h * HDD + 8 * nt + 2 * c;
        size_t idx0 = ((size_t)b * TT + row0) * CC + col;
        size_t idx1 = ((size_t)b * TT + row1) * CC + col;
        uint32_t h0, lo0, h1, lo1;
        split2(O[nt][0] * i0, O[nt][1] * i0, h0, lo0);
        split2(O[nt][2] * i1, O[nt][3] * i1, h1, lo1);
        *(uint32_t*)&ohi[idx0] = h0;
        *(uint32_t*)&olo[idx0] = lo0;
        *(uint32_t*)&ohi[idx1] = h1;
        *(uint32_t*)&olo[idx1] = lo1;
    }
}

// ---------------- LayerNorm + residual ----------------
__device__ __forceinline__ float block_sum(float v, float* red) {
    const int lane = threadIdx.x & 31, w = threadIdx.x >> 5;
#pragma unroll
    for (int o = 16; o; o >>= 1) v += __shfl_xor_sync(0xffffffffu, v, o);
    if (lane == 0) red[w] = v;
    __syncthreads();
    if (w == 0) {
        float s = (lane < 8) ? red[lane] : 0.0f;
#pragma unroll
        for (int o = 4; o; o >>= 1) s += __shfl_xor_sync(0xffffffffu, s, o);
        if (lane == 0) red[0] = s;
    }
    __syncthreads();
    float rr = red[0];
    __syncthreads();
    return rr;
}

template<bool SPLIT>
__global__ void __launch_bounds__(256)
ln_res_kernel(const float* __restrict__ res, const float* __restrict__ y,
              const float* __restrict__ g, const float* __restrict__ be,
              float* __restrict__ out,
              __nv_bfloat16* __restrict__ ohi, __nv_bfloat16* __restrict__ olo)
{
    __shared__ float red[8];
    const int row = blockIdx.x;
    const int t = threadIdx.x;
    const float* yr = y + (size_t)row * CC;

    float v[4];
    float s = 0.0f;
#pragma unroll
    for (int i = 0; i < 4; ++i) { v[i] = yr[t + i * 256]; s += v[i]; }
    const float mean = block_sum(s, red) * (1.0f / CC);

    float sq = 0.0f;
#pragma unroll
    for (int i = 0; i < 4; ++i) { float d = v[i] - mean; sq += d * d; }
    const float var = block_sum(sq, red) * (1.0f / CC);
    const float rstd = rsqrtf(var + 1e-5f);

    const float* rr = res + (size_t)row * CC;
    float* orow = out + (size_t)row * CC;
#pragma unroll
    for (int i = 0; i < 4; ++i) {
        int cix = t + i * 256;
        float o = rr[cix] + (v[i] - mean) * rstd * g[cix] + be[cix];
        orow[cix] = o;
        if (SPLIT) {
            __nv_bfloat16 hh = __float2bfloat16_rn(o);
            ohi[(size_t)row * CC + cix] = hh;
            olo[(size_t)row * CC + cix] = __float2bfloat16_rn(o - __bfloat162float(hh));
        }
    }
}

// ---------------- launch ----------------
extern "C" void kernel_launch(void* const* d_in, const int* in_sizes, int n_in,
                              void* d_out, int out_size)
{
    const float* x      = (const float*)d_in[0];
    const float* w_attn = (const float*)d_in[1];
    const float* b_attn = (const float*)d_in[2];
    const float* wa1    = (const float*)d_in[3];
    const float* ba1    = (const float*)d_in[4];
    const float* wa2    = (const float*)d_in[5];
    const float* ba2    = (const float*)d_in[6];
    const float* g1     = (const float*)d_in[7];
    const float* be1    = (const float*)d_in[8];
    const float* wf1    = (const float*)d_in[9];
    const float* bf1    = (const float*)d_in[10];
    const float* wf2    = (const float*)d_in[11];
    const float* bf2    = (const float*)d_in[12];
    const float* g2     = (const float*)d_in[13];
    const float* be2    = (const float*)d_in[14];
    float* out = (float*)d_out;

    float *x1, *y;
    cudaGetSymbolAddress((void**)&x1, g_x1);
    cudaGetSymbolAddress((void**)&y,  g_y);

    __nv_bfloat16 *wqkv_hi, *wqkv_lo, *wa1_hi, *wa1_lo, *wa2_hi, *wa2_lo,
                  *wf1_hi, *wf1_lo, *wf2_hi, *wf2_lo, *ahi, *alo, *hhi, *hlo,
                  *qkvh, *qkvl;
    cudaGetSymbolAddress((void**)&wqkv_hi, g_wqkv_hi);
    cudaGetSymbolAddress((void**)&wqkv_lo, g_wqkv_lo);
    cudaGetSymbolAddress((void**)&wa1_hi,  g_wa1_hi);
    cudaGetSymbolAddress((void**)&wa1_lo,  g_wa1_lo);
    cudaGetSymbolAddress((void**)&wa2_hi,  g_wa2_hi);
    cudaGetSymbolAddress((void**)&wa2_lo,  g_wa2_lo);
    cudaGetSymbolAddress((void**)&wf1_hi,  g_wf1_hi);
    cudaGetSymbolAddress((void**)&wf1_lo,  g_wf1_lo);
    cudaGetSymbolAddress((void**)&wf2_hi,  g_wf2_hi);
    cudaGetSymbolAddress((void**)&wf2_lo,  g_wf2_lo);
    cudaGetSymbolAddress((void**)&ahi,     g_ahi);
    cudaGetSymbolAddress((void**)&alo,     g_alo);
    cudaGetSymbolAddress((void**)&hhi,     g_hhi);
    cudaGetSymbolAddress((void**)&hlo,     g_hlo);
    cudaGetSymbolAddress((void**)&qkvh,    g_qkvh);
    cudaGetSymbolAddress((void**)&qkvl,    g_qkvl);

    cudaFuncSetAttribute(attn_mma_kernel, cudaFuncAttributeMaxDynamicSharedMemorySize, ASMEM);
    cudaFuncSetAttribute(gemm_mma_kernel<0>, cudaFuncAttributeMaxDynamicSharedMemorySize, GSMEM);
    cudaFuncSetAttribute(gemm_mma_kernel<1>, cudaFuncAttributeMaxDynamicSharedMemorySize, GSMEM);
    cudaFuncSetAttribute(gemm_mma_kernel<2>, cudaFuncAttributeMaxDynamicSharedMemorySize, GSMEM);

    // weight transpose + bf16 split
    cvt_wt_kernel<<<dim3(C3 / 32, CC / 32), 256>>>(w_attn, wqkv_hi, wqkv_lo, CC, C3);
    cvt_wt_kernel<<<dim3(C4 / 32, CC / 32), 256>>>(wa1, wa1_hi, wa1_lo, CC, C4);
    cvt_wt_kernel<<<dim3(CC / 32, C4 / 32), 256>>>(wa2, wa2_hi, wa2_lo, C4, CC);
    cvt_wt_kernel<<<dim3(C4 / 32, CC / 32), 256>>>(wf1, wf1_hi, wf1_lo, CC, C4);
    cvt_wt_kernel<<<dim3(CC / 32, C4 / 32), 256>>>(wf2, wf2_hi, wf2_lo, C4, CC);

    // 1) qkv = x @ w_attn + b_attn -> split bf16
    cvt_act_kernel<<<(MTOK * CC) / 1024, 256>>>(x, ahi, alo, MTOK * CC);
    gemm_mma_kernel<2><<<dim3(C3 / 128, MTOK / 128), 256, GSMEM>>>(
        ahi, alo, wqkv_hi, wqkv_lo, b_attn, nullptr, qkvh, qkvl, C3, CC);
    // 2) attention (HMMA) -> split bf16 att
    attn_mma_kernel<<<dim3(TT / 64, NHH, BB), 128, ASMEM>>>(qkvh, qkvl, ahi, alo);
    // 3) h = gelu(att @ wa1 + ba1) -> split bf16
    gemm_mma_kernel<1><<<dim3(C4 / 128, MTOK / 128), 256, GSMEM>>>(
        ahi, alo, wa1_hi, wa1_lo, ba1, nullptr, hhi, hlo, C4, CC);
    // 4) y = h @ wa2 + ba2
    gemm_mma_kernel<0><<<dim3(CC / 128, MTOK / 128), 256, GSMEM>>>(
        hhi, hlo, wa2_hi, wa2_lo, ba2, y, nullptr, nullptr, CC, C4);
    // 5) x1 = x + ln(y); emit split bf16 x1
    ln_res_kernel<true><<<MTOK, 256>>>(x, y, g1, be1, x1, ahi, alo);
    // 6) h = gelu(x1 @ wf1 + bf1) -> split bf16
    gemm_mma_kernel<1><<<dim3(C4 / 128, MTOK / 128), 256, GSMEM>>>(
        ahi, alo, wf1_hi, wf1_lo, bf1, nullptr, hhi, hlo, C4, CC);
    // 7) y = h @ wf2 + bf2
    gemm_mma_kernel<0><<<dim3(CC / 128, MTOK / 128), 256, GSMEM>>>(
        hhi, hlo, wf2_hi, wf2_lo, bf2, y, nullptr, nullptr, CC, C4);
    // 8) out = x1 + ln(y)
    ln_res_kernel<false><<<MTOK, 256>>>(x1, y, g2, be2, out, nullptr, nullptr);
}